// round 13
// baseline (speedup 1.0000x reference)
#include <cuda_runtime.h>

#define BB 128
#define NN 512
#define CC 7
#define HH 64
#define KK 16
#define EPSF 1e-5f

typedef unsigned long long ull;

// ---------------- scratch (device globals: allocation-free) ----------------
__device__ __align__(16) float g_hA[BB*NN*HH];      // 16.8 MB
__device__ __align__(16) float g_hB[BB*NN*HH];      // 16.8 MB
__device__ __align__(16) float g_ac[BB*NN*2*HH];    // 33.5 MB
__device__ float g_sq[BB*NN];
__device__ int   g_idx[BB*NN*KK];
__device__ float g_wfT[2*HH*128];
__device__ float g_wb[2*HH];

// ---------------- packed fp32x2 helpers ------------------------------------
__device__ __forceinline__ ull fma2(ull a, ull b, ull c){
    ull d; asm("fma.rn.f32x2 %0, %1, %2, %3;" : "=l"(d) : "l"(a), "l"(b), "l"(c)); return d;
}
__device__ __forceinline__ ull add2(ull a, ull b){
    ull d; asm("add.rn.f32x2 %0, %1, %2;" : "=l"(d) : "l"(a), "l"(b)); return d;
}
__device__ __forceinline__ float lo2(ull a){ return __uint_as_float((unsigned)a); }
__device__ __forceinline__ float hi2(ull a){ return __uint_as_float((unsigned)(a >> 32)); }
__device__ __forceinline__ ull pk2(float lo, float hi){
    ull d; asm("mov.b64 %0, {%1,%2};" : "=l"(d) : "f"(lo), "f"(hi)); return d;
}

// ---------------- legacy tensor-core mma (baseline PTX, works on sm_103) ----
__device__ __forceinline__ void mma8(float& d0, float& d1, float& d2, float& d3,
                                     float a0, float a1, float a2, float a3,
                                     float b0, float b1){
    asm volatile("mma.sync.aligned.m16n8k8.row.col.f32.tf32.tf32.f32 "
        "{%0,%1,%2,%3}, {%4,%5,%6,%7}, {%8,%9}, {%0,%1,%2,%3};"
        : "+f"(d0), "+f"(d1), "+f"(d2), "+f"(d3)
        : "r"(__float_as_uint(a0)), "r"(__float_as_uint(a1)),
          "r"(__float_as_uint(a2)), "r"(__float_as_uint(a3)),
          "r"(__float_as_uint(b0)), "r"(__float_as_uint(b1)));
}

// ---------------------------------------------------------------------------
// k_prep: fold BN scale into edgeconv weights, TRANSPOSED layout [r][hh][o]
// ---------------------------------------------------------------------------
__global__ void k_prep(const float* __restrict__ wnb,
                       const float* __restrict__ gnb,
                       const float* __restrict__ bnb)
{
    int i = blockIdx.x*256 + threadIdx.x;
    if (i < 2*HH) g_wb[i] = bnb[i];
    if (i >= 2*HH*128) return;
    int r   = i >> 13;
    int rem = i & 8191;
    int hh  = rem >> 7;
    int o   = rem & 127;
    float inv = rsqrtf(1.0f + EPSF);
    float v;
    if (o < HH){
        float s = gnb[r*HH + o] * inv;
        v = (wnb[(r*HH + o)*128 + hh] - wnb[(r*HH + o)*128 + 64 + hh]) * s;
    } else {
        int oo = o - HH;
        float s = gnb[r*HH + oo] * inv;
        v = wnb[(r*HH + oo)*128 + 64 + hh] * s;
    }
    g_wfT[i] = v;
}

// ---------------------------------------------------------------------------
// k_input: h = relu(bn2(W2 relu(bn1(W1 x)))), fused row-norm (g_sq).
// ---------------------------------------------------------------------------
__global__ void k_input(const float* __restrict__ x,
                        const float* __restrict__ w1, const float* __restrict__ g1,
                        const float* __restrict__ b1,
                        const float* __restrict__ w2, const float* __restrict__ g2,
                        const float* __restrict__ b2)
{
    __shared__ float w1s[HH*CC];
    __shared__ float w2sT[HH][HH];
    __shared__ float xs[16][CC];
    __shared__ __align__(16) float h1s[16][HH];
    __shared__ float part[32];
    int tx = threadIdx.x, ty = threadIdx.y;
    int tid = ty*64 + tx;
    int p0 = blockIdx.x*16;
    int b  = p0 / NN;
    int n0 = p0 % NN;

    for (int i = tid; i < HH*CC; i += 1024) w1s[i] = w1[i];
    for (int i = tid; i < HH*HH; i += 1024) { int o = i>>6, hh = i&63; w2sT[hh][o] = w2[i]; }
    if (tid < 16*CC) { int c = tid/16, i = tid%16; xs[i][c] = x[b*CC*NN + c*NN + n0 + i]; }
    __syncthreads();

    float inv = rsqrtf(1.0f + EPSF);
    float s1 = g1[tx]*inv, bb1 = b1[tx];
    float s2 = g2[tx]*inv, bb2 = b2[tx];

    {
        float acc = 0.f;
        #pragma unroll
        for (int c = 0; c < CC; c++) acc = fmaf(w1s[tx*CC + c], xs[ty][c], acc);
        h1s[ty][tx] = fmaxf(acc*s1 + bb1, 0.f);
    }
    __syncthreads();
    float val;
    {
        float a0=0,a1=0,a2=0,a3=0;
        const float4* hp = reinterpret_cast<const float4*>(h1s[ty]);
        #pragma unroll
        for (int q = 0; q < 16; q++){
            float4 v = hp[q];
            int hh = q*4;
            a0 = fmaf(w2sT[hh+0][tx], v.x, a0);
            a1 = fmaf(w2sT[hh+1][tx], v.y, a1);
            a2 = fmaf(w2sT[hh+2][tx], v.z, a2);
            a3 = fmaf(w2sT[hh+3][tx], v.w, a3);
        }
        val = fmaxf(((a0+a1)+(a2+a3))*s2 + bb2, 0.f);
        g_hA[(p0+ty)*HH + tx] = val;
    }
    float ss = val*val;
    #pragma unroll
    for (int off = 16; off; off >>= 1) ss += __shfl_down_sync(0xffffffffu, ss, off);
    if ((tx & 31) == 0) part[tid >> 5] = ss;
    __syncthreads();
    if (tx == 0) g_sq[p0 + ty] = part[2*ty] + part[2*ty + 1];
}

// ---------------------------------------------------------------------------
// kNN v7 (mma.sync tf32 filter + exact fp32 refine).
// tf32 truncation bound: 2|dot_err| <= 2^-9 (sqn+sqm) < 0.006(sqn+sqm) margin
// => mask is a provable superset of the true top-16. Refine recomputes exact
// fp32 distances with the SAME chain grouping as the scalar kernel, inserted
// in index order via sortable-u64 evict-max => identical set + tie semantics.
//
// Smem floats: A[128][68] | T[64][68] | D[128][65] | SQ[64] | KEEP (16x128 ull)
// ---------------------------------------------------------------------------
#define SM_A  0
#define SM_T  8704
#define SM_D  13056
#define SM_SQ 21376
#define SM_KP 21440
#define KSM_BYTES (21440*4 + 16*128*8)   // 102144 bytes

__global__ __launch_bounds__(128) void k_knn_mma(int src)
{
    extern __shared__ __align__(16) float sm[];
    float* As = sm + SM_A;
    float* Ts = sm + SM_T;
    float* Ds = sm + SM_D;
    float* SQ = sm + SM_SQ;
    ull*  KPB = (ull*)(sm + SM_KP);

    const float* h = src ? g_hB : g_hA;
    int tid = threadIdx.x, lane = tid & 31, warp = tid >> 5;
    int b = blockIdx.y, q0 = blockIdx.x*128;
    int row = b*NN + q0 + tid;

    // load A (this block's 128 query rows), stride-68 padded
    {
        const float4* hg = (const float4*)(h + (b*NN + q0)*HH);
        #pragma unroll
        for (int i = 0; i < 16; i++){
            int idx = tid + i*128;
            *(float4*)(As + (idx>>4)*68 + (idx&15)*4) = hg[idx];
        }
    }
    // tile 0
    {
        const float4* tg = (const float4*)(h + b*NN*HH);
        #pragma unroll
        for (int i = 0; i < 8; i++){
            int idx = tid + i*128;
            *(float4*)(Ts + (idx>>4)*68 + (idx&15)*4) = tg[idx];
        }
        if (tid < 64) SQ[tid] = g_sq[b*NN + tid];
    }

    float sqn = g_sq[row];
    ull* keepc = KPB + tid;                 // stride 128
    #pragma unroll
    for (int j = 0; j < KK; j++) keepc[j*128] = ~0ull;
    ull maxA = ~0ull, maxB = ~0ull;
    int wsA = 0, wsB = 0;
    ull wkey = ~0ull;

    // prefetch tile 1
    float4 pf[8]; float psq = 0.f;
    {
        const float4* ng = (const float4*)(h + (b*NN + 64)*HH);
        #pragma unroll
        for (int i = 0; i < 8; i++) pf[i] = ng[tid + i*128];
        if (tid < 64) psq = g_sq[b*NN + 64 + tid];
    }

    #define INSERT(key) {                                                     \
        ull wk = (maxA > maxB) ? maxA : maxB;                                 \
        if ((key) < wk){                                                      \
            bool ina = (maxA > maxB);                                         \
            int base = ina ? 0 : 8;                                           \
            int ws   = ina ? wsA : wsB;                                       \
            keepc[(base + ws)*128] = (key);                                   \
            ull mx = keepc[base*128]; int ms = 0;                             \
            _Pragma("unroll")                                                 \
            for (int j = 1; j < 8; j++){                                      \
                ull kj = keepc[(base + j)*128];                               \
                if (kj > mx){ mx = kj; ms = j; }                              \
            }                                                                 \
            if (ina){ maxA = mx; wsA = ms; } else { maxB = mx; wsB = ms; }    \
        }                                                                     \
    }

    int grp = lane >> 2, tig = lane & 3;

    for (int t = 0; t < 8; t++){
        __syncthreads();                       // tile t visible

        // ---- MMA phase: this warp computes D rows [32w, 32w+32) x 64 ----
        #pragma unroll
        for (int rg = 0; rg < 2; rg++){
            int r0 = warp*32 + rg*16;
            float af[32];
            #pragma unroll
            for (int k = 0; k < 8; k++){
                const float* Ab = As + (r0 + grp)*68 + k*8 + tig;
                af[4*k+0] = Ab[0];
                af[4*k+1] = Ab[8*68];
                af[4*k+2] = Ab[4];
                af[4*k+3] = Ab[8*68 + 4];
            }
            #pragma unroll
            for (int cg = 0; cg < 8; cg++){
                float d0=0.f, d1=0.f, d2=0.f, d3=0.f;
                #pragma unroll
                for (int k = 0; k < 8; k++){
                    const float* Bb = Ts + (cg*8 + grp)*68 + k*8 + tig;
                    mma8(d0,d1,d2,d3, af[4*k+0],af[4*k+1],af[4*k+2],af[4*k+3],
                         Bb[0], Bb[4]);
                }
                float* Dp = Ds + (r0 + grp)*65 + cg*8 + 2*tig;
                Dp[0] = d0; Dp[1] = d1;
                Dp[8*65] = d2; Dp[8*65 + 1] = d3;
            }
        }
        __syncthreads();                       // D visible

        // ---- loose mask (tf32 dots + provable margin) ----
        unsigned whi = (unsigned)(wkey >> 32);
        ull mask = 0ull;
        {
            const float* drow = Ds + tid*65;
            #pragma unroll
            for (int c = 0; c < 64; c++){
                float dot = drow[c];
                float s = sqn + SQ[c];
                float dl = fmaxf(fmaf(-0.006f, s, fmaf(-2.0f, dot, s)), 0.f);
                mask |= (ull)(__float_as_uint(dl) <= whi) << c;
            }
        }

        // ---- exact fp32 refine of masked candidates (index order) ----
        const float4* qp = (const float4*)(As + tid*68);
        while (__any_sync(0xffffffffu, mask != 0ull)){
            bool act = (mask != 0ull);
            int c = act ? (__ffsll((long long)mask) - 1) : 0;
            mask &= (mask - 1ull);
            const float4* tp = (const float4*)(Ts + c*68);
            ull a0=0, a1=0, a2=0, a3=0;
            #pragma unroll
            for (int q = 0; q < 8; q++){
                float4 qv = qp[q]; float4 cv = tp[q];
                a0 = fma2(pk2(qv.x,qv.y), pk2(cv.x,cv.y), a0);
                a1 = fma2(pk2(qv.z,qv.w), pk2(cv.z,cv.w), a1);
            }
            #pragma unroll
            for (int q = 8; q < 16; q++){
                float4 qv = qp[q]; float4 cv = tp[q];
                a2 = fma2(pk2(qv.x,qv.y), pk2(cv.x,cv.y), a2);
                a3 = fma2(pk2(qv.z,qv.w), pk2(cv.z,cv.w), a3);
            }
            ull sv = add2(add2(a0,a2), add2(a1,a3));
            float dot = lo2(sv) + hi2(sv);
            float d = fmaxf(sqn + SQ[c] - 2.0f*dot, 0.f);
            ull key = ((ull)__float_as_uint(d) << 32) | (unsigned)(t*64 + c);
            if (act && key < wkey){
                INSERT(key);
                wkey = (maxA > maxB) ? maxA : maxB;
            }
        }
        __syncthreads();                       // refine done reading tile t

        if (t < 7){
            #pragma unroll
            for (int i = 0; i < 8; i++){
                int idx = tid + i*128;
                *(float4*)(Ts + (idx>>4)*68 + (idx&15)*4) = pf[i];
            }
            if (tid < 64) SQ[tid] = psq;
            if (t < 6){
                const float4* ng = (const float4*)(h + (b*NN + (t+2)*64)*HH);
                #pragma unroll
                for (int i = 0; i < 8; i++) pf[i] = ng[tid + i*128];
                if (tid < 64) psq = g_sq[b*NN + (t+2)*64 + tid];
            }
        }
    }
    #undef INSERT

    #pragma unroll
    for (int j = 0; j < KK; j++)
        g_idx[row*KK + j] = b*NN + (int)(unsigned)(keepc[j*128] & 0xffffffffull);
}

// ---------------------------------------------------------------------------
// a/c GEMM (unchanged from the 776us version)
// ---------------------------------------------------------------------------
__global__ __launch_bounds__(128) void k_ac(int r, int src)
{
    const float* h = src ? g_hB : g_hA;
    __shared__ __align__(16) float hs[64*HH];
    int t  = threadIdx.x;
    int p0 = blockIdx.x*64;

    ull wq[32];
    const float* wbase = g_wfT + r*8192;
    #pragma unroll
    for (int j = 0; j < 32; j++){
        float wa = wbase[(2*j  )*128 + t];
        float wb = wbase[(2*j+1)*128 + t];
        wq[j] = pk2(wa, wb);
    }
    float bias = (t < HH) ? g_wb[r*HH + t] : 0.f;

    const float4* src4 = reinterpret_cast<const float4*>(h + p0*HH);
    float4* hs4 = reinterpret_cast<float4*>(hs);
    for (int i = t; i < 1024; i += 128) hs4[i] = src4[i];
    __syncthreads();

    #pragma unroll 1
    for (int p = 0; p < 64; p += 2){
        const longlong2* hp = reinterpret_cast<const longlong2*>(hs + p*HH);
        ull a0=0, a1=0, a2=0, a3=0;
        ull c0=0, c1=0, c2=0, c3=0;
        #pragma unroll
        for (int q = 0; q < 8; q++){
            longlong2 v = hp[q];
            longlong2 w = hp[q+16];
            a0 = fma2(wq[2*q],   (ull)v.x, a0);
            a1 = fma2(wq[2*q+1], (ull)v.y, a1);
            c0 = fma2(wq[2*q],   (ull)w.x, c0);
            c1 = fma2(wq[2*q+1], (ull)w.y, c1);
        }
        #pragma unroll
        for (int q = 8; q < 16; q++){
            longlong2 v = hp[q];
            longlong2 w = hp[q+16];
            a2 = fma2(wq[2*q],   (ull)v.x, a2);
            a3 = fma2(wq[2*q+1], (ull)v.y, a3);
            c2 = fma2(wq[2*q],   (ull)w.x, c2);
            c3 = fma2(wq[2*q+1], (ull)w.y, c3);
        }
        ull sv = add2(add2(a0,a2), add2(a1,a3));
        ull sw = add2(add2(c0,c2), add2(c1,c3));
        g_ac[(p0+p  )*128 + t] = bias + lo2(sv) + hi2(sv);
        g_ac[(p0+p+1)*128 + t] = bias + lo2(sw) + hi2(sw);
    }
}

// ---------------------------------------------------------------------------
// gather-max + fused row-norm (unchanged)
// ---------------------------------------------------------------------------
__global__ void k_gmax(int src)
{
    float* out = src ? g_hA : g_hB;
    __shared__ int idxs[8*KK];
    __shared__ float part[16];
    int tx = threadIdx.x, ty = threadIdx.y;
    int tid = ty*64 + tx;
    int p0 = blockIdx.x*8;
    if (tid < 8*KK) idxs[tid] = g_idx[p0*KK + tid];
    __syncthreads();
    int p = p0 + ty;
    float a = g_ac[p*128 + tx];
    float m = 0.f;
    #pragma unroll
    for (int k = 0; k < KK; k++){
        int nb = idxs[ty*KK + k];
        m = fmaxf(m, a + g_ac[nb*128 + 64 + tx]);
    }
    out[p*HH + tx] = m;

    float ss = m*m;
    #pragma unroll
    for (int off = 16; off; off >>= 1) ss += __shfl_down_sync(0xffffffffu, ss, off);
    if ((tx & 31) == 0) part[tid >> 5] = ss;
    __syncthreads();
    if (tx == 0) g_sq[p] = part[2*ty] + part[2*ty + 1];
}

// ---------------------------------------------------------------------------
// head (unchanged)
// ---------------------------------------------------------------------------
__global__ void k_head(int src,
    const float* __restrict__ w1, const float* __restrict__ g1,
    const float* __restrict__ b1,
    const float* __restrict__ w2, const float* __restrict__ b2,
    float* __restrict__ out)
{
    const float* h = src ? g_hB : g_hA;
    __shared__ float w1sT[HH][HH];
    __shared__ __align__(16) float hs[16][HH];
    __shared__ float parts[16][2];
    int tx = threadIdx.x, ty = threadIdx.y;
    int tid = ty*64 + tx;
    int p0 = blockIdx.x*16;

    for (int i = tid; i < HH*HH; i += 1024){ int o = i>>6, hh = i&63; w1sT[hh][o] = w1[i]; }
    hs[ty][tx] = h[(p0+ty)*HH + tx];
    __syncthreads();

    float inv = rsqrtf(1.0f + EPSF);
    float s = g1[tx]*inv, bb = b1[tx];
    float a0=0,a1=0,a2=0,a3=0;
    const float4* hp = reinterpret_cast<const float4*>(hs[ty]);
    #pragma unroll
    for (int q = 0; q < 16; q++){
        float4 v = hp[q];
        int hh = q*4;
        a0 = fmaf(w1sT[hh+0][tx], v.x, a0);
        a1 = fmaf(w1sT[hh+1][tx], v.y, a1);
        a2 = fmaf(w1sT[hh+2][tx], v.z, a2);
        a3 = fmaf(w1sT[hh+3][tx], v.w, a3);
    }
    float u = fmaxf(((a0+a1)+(a2+a3))*s + bb, 0.f);
    float v = u * w2[tx];
    #pragma unroll
    for (int off = 16; off; off >>= 1) v += __shfl_down_sync(0xffffffffu, v, off);
    if ((tx & 31) == 0) parts[ty][tx >> 5] = v;
    __syncthreads();
    if (tx == 0) out[p0 + ty] = parts[ty][0] + parts[ty][1] + b2[0];
}

// ---------------------------------------------------------------------------
extern "C" void kernel_launch(void* const* d_in, const int* in_sizes, int n_in,
                              void* d_out, int out_size)
{
    (void)in_sizes; (void)n_in; (void)out_size;
    const float* x    = (const float*)d_in[0];
    const float* w_t1 = (const float*)d_in[1];
    const float* g_t1 = (const float*)d_in[2];
    const float* b_t1 = (const float*)d_in[3];
    const float* w_t2 = (const float*)d_in[4];
    const float* g_t2 = (const float*)d_in[5];
    const float* b_t2 = (const float*)d_in[6];
    const float* w_nb = (const float*)d_in[7];
    const float* g_nb = (const float*)d_in[8];
    const float* b_nb = (const float*)d_in[9];
    const float* w_s1 = (const float*)d_in[10];
    const float* g_s1 = (const float*)d_in[11];
    const float* b_s1 = (const float*)d_in[12];
    const float* w_s2 = (const float*)d_in[13];
    const float* b_s2 = (const float*)d_in[14];
    float* out = (float*)d_out;

    cudaFuncSetAttribute(k_knn_mma, cudaFuncAttributeMaxDynamicSharedMemorySize, KSM_BYTES);

    k_prep<<<64, 256>>>(w_nb, g_nb, b_nb);
    k_input<<<BB*NN/16, dim3(64,16)>>>(x, w_t1, g_t1, b_t1, w_t2, g_t2, b_t2);

    for (int r = 0; r < 2; r++){
        k_knn_mma<<<dim3(4,128), 128, KSM_BYTES>>>(r);
        k_ac     <<<BB*NN/64, 128>>>(r, r);
        k_gmax   <<<BB*NN/8, dim3(64,8)>>>(r);
    }

    k_head<<<BB*NN/16, dim3(64,16)>>>(0, w_s1, g_s1, b_s1, w_s2, b_s2, out);
}